// round 16
// baseline (speedup 1.0000x reference)
#include <cuda_runtime.h>
#include <math.h>
#include <stdint.h>

// ---------------------------------------------------------------------------
// Problem: B=8, C=512, H=W=48 (HW=2304); stride-2 conv -> 24x24=576
// All GEMMs in NT form: C[M,N] = A[M,K] * B[N,K]^T.
// MODE 0: BF16X2 compensated (3 bf16 m16n8k16 MMAs per k16) -- pre-softmax
//         chain (G1, G2, G4, G5).
// MODE 1: plain tf32 m16n8k8 -- post-softmax (G6a + fused G3/G6b).
// fp16.f32-accum measured SLOW on sm_103 -- do not use.
// G6 re-associated: out_p = attn_c * (attn_p * xf^T)^T.
// FUSED G36: since G3 (out_c = attn_c*xT^T) and G6b (out_p = attn_c*tT^T)
// share A and shape, run one tf32 GEMM with N=4608: B/C selected per block
// (2304 % BN == 0). G1 NF=6; G4 NF=4 (wave fill). 2-stage cp.async.
// ---------------------------------------------------------------------------
#define BATCH 8

// scratch layout (floats)
#define SZ_COLT  (8L*576*4608)
#define SZ_XT    (8L*2304*512)
#define SZ_WQCKC (1536L*4608)
#define SZ_WQKP  (128L*512)
#define SZ_QCKC  (8L*1536*576)
#define SZ_EN    (8L*1024*512)
#define SZ_QKPT  (8L*2304*128)
#define SZ_EP    (8L*2304*2304)
#define SZ_TT    (8L*2304*512)

#define OFF_COLT  0L
#define OFF_XT    (OFF_COLT + SZ_COLT)
#define OFF_WQCKC (OFF_XT + SZ_XT)
#define OFF_WQKP  (OFF_WQCKC + SZ_WQCKC)
#define OFF_QCKC  (OFF_WQKP + SZ_WQKP)
#define OFF_EN    (OFF_QCKC + SZ_QCKC)
#define OFF_QKPT  (OFF_EN + SZ_EN)
#define OFF_EP    (OFF_QKPT + SZ_QKPT)
#define OFF_TT    (OFF_EP + SZ_EP)
#define OFF_BIAS  (OFF_TT + SZ_TT)
#define SZ_TOTAL  (OFF_BIAS + 4096)

__device__ float g_scratch[SZ_TOTAL];

// ---------------------------------------------------------------------------
// helpers
// ---------------------------------------------------------------------------
__device__ __forceinline__ uint32_t f2tf32(float f) {
    uint32_t u;
    asm("cvt.rna.tf32.f32 %0, %1;" : "=r"(u) : "f"(f));
    return u;
}
__device__ __forceinline__ void mma_tf32(float* d, const uint32_t* a, const uint32_t* b) {
    asm volatile(
        "mma.sync.aligned.m16n8k8.row.col.f32.tf32.tf32.f32 "
        "{%0,%1,%2,%3}, {%4,%5,%6,%7}, {%8,%9}, {%0,%1,%2,%3};"
        : "+f"(d[0]), "+f"(d[1]), "+f"(d[2]), "+f"(d[3])
        : "r"(a[0]), "r"(a[1]), "r"(a[2]), "r"(a[3]), "r"(b[0]), "r"(b[1]));
}
__device__ __forceinline__ void mma_bf16(float* d, const uint32_t* a, const uint32_t* b) {
    asm volatile(
        "mma.sync.aligned.m16n8k16.row.col.f32.bf16.bf16.f32 "
        "{%0,%1,%2,%3}, {%4,%5,%6,%7}, {%8,%9}, {%0,%1,%2,%3};"
        : "+f"(d[0]), "+f"(d[1]), "+f"(d[2]), "+f"(d[3])
        : "r"(a[0]), "r"(a[1]), "r"(a[2]), "r"(a[3]), "r"(b[0]), "r"(b[1]));
}
// hi = truncate-to-bf16 (exact in fp32), lo = bf16(f - hi). Pack k,k+1 pairs.
__device__ __forceinline__ void split_pair(float f0, float f1, uint32_t& h, uint32_t& l) {
    uint32_t u0 = __float_as_uint(f0), u1 = __float_as_uint(f1);
    h = __byte_perm(u0, u1, 0x7632);               // {f1.hi16, f0.hi16}
    float l0 = f0 - __uint_as_float(u0 & 0xFFFF0000u);
    float l1 = f1 - __uint_as_float(u1 & 0xFFFF0000u);
    asm("cvt.rn.bf16x2.f32 %0, %1, %2;" : "=r"(l) : "f"(l1), "f"(l0));
}
#define CPASYNC(dst, src) \
    asm volatile("cp.async.cg.shared.global [%0], [%1], 16;" :: "r"(dst), "l"(src) : "memory")

// ---------------------------------------------------------------------------
// NT GEMM via warp MMA. 128 threads (4 warps, 2x2). Block 128 x (NF*16) x 32.
// Warp tile 64 x (NF*8). SMEM rows padded to 36 floats. 2-stage cp.async.
// Requires M%128==0, N%(NF*16)==0, K%32==0.
// Split-N fusion: blocks with n0 >= nsplit read B2 / write C2 at col-nsplit
// (nsplit must be a multiple of BN; pass huge nsplit to disable).
// ---------------------------------------------------------------------------
#define GBM 128
#define GBK 32
#define LDSA 36

template <int MODE, int NF>
__global__ __launch_bounds__(128) void mma_gemm(
    const float* __restrict__ A, const float* __restrict__ B,
    float* __restrict__ C, const float* __restrict__ bias,
    const float* __restrict__ B2, float* __restrict__ C2, int nsplit,
    int M, int N, int K, int lda, int ldb, int ldc,
    long sA, long sB, long sC, int bias_mode)
{
    constexpr int BN = NF * 16;
    constexpr int A_FL = 128 * LDSA;
    constexpr int B_FL = BN * LDSA;
    constexpr int NBC = BN / 16;

    extern __shared__ float sm[];
    float* As[2] = { sm, sm + A_FL };
    float* Bs[2] = { sm + 2 * A_FL, sm + 2 * A_FL + B_FL };

    const int tid = threadIdx.x;
    const int bz = blockIdx.z;
    const int m0 = blockIdx.y * GBM;
    int n0 = blockIdx.x * BN;

    const float* Bsel = B;
    float* Csel = C;
    if (n0 >= nsplit) { Bsel = B2; Csel = C2; n0 -= nsplit; }
    A    += (long)bz * sA;
    Bsel += (long)bz * sB;
    Csel += (long)bz * sC;

    // cp.async mapping: 16B chunks, rows strided by 16
    const int c8 = tid & 7;
    const int r0 = tid >> 3;
    const float* gA = A + (long)(m0 + r0) * lda + c8 * 4;
    const float* gB = Bsel + (long)(n0 + r0) * ldb + c8 * 4;
    uint32_t sA0 = (uint32_t)__cvta_generic_to_shared(As[0] + r0 * LDSA + c8 * 4);
    uint32_t sA1 = (uint32_t)__cvta_generic_to_shared(As[1] + r0 * LDSA + c8 * 4);
    uint32_t sB0 = (uint32_t)__cvta_generic_to_shared(Bs[0] + r0 * LDSA + c8 * 4);
    uint32_t sB1 = (uint32_t)__cvta_generic_to_shared(Bs[1] + r0 * LDSA + c8 * 4);

    const int NT = K / GBK;

    const int warp = tid >> 5, lane = tid & 31;
    const int wm = (warp & 1) * 64;
    const int wn = (warp >> 1) * (NF * 8);
    const int gid = lane >> 2, tg = lane & 3;

    float acc[4][NF][4];
#pragma unroll
    for (int i = 0; i < 4; i++)
#pragma unroll
        for (int j = 0; j < NF; j++)
#pragma unroll
            for (int c = 0; c < 4; c++) acc[i][j][c] = 0.0f;

    // prologue: stage 0
    {
#pragma unroll
        for (int i = 0; i < 8; i++)
            CPASYNC(sA0 + i * (16 * LDSA * 4), gA + (long)i * 16 * lda);
#pragma unroll
        for (int i = 0; i < NBC; i++)
            CPASYNC(sB0 + i * (16 * LDSA * 4), gB + (long)i * 16 * ldb);
        asm volatile("cp.async.commit_group;" ::: "memory");
    }

    for (int kt = 0; kt < NT; kt++) {
        asm volatile("cp.async.wait_group 0;" ::: "memory");
        __syncthreads();

        if (kt + 1 < NT) {
            const long koff = (long)(kt + 1) * GBK;
            const uint32_t dA = ((kt + 1) & 1) ? sA1 : sA0;
            const uint32_t dB = ((kt + 1) & 1) ? sB1 : sB0;
#pragma unroll
            for (int i = 0; i < 8; i++)
                CPASYNC(dA + i * (16 * LDSA * 4), gA + koff + (long)i * 16 * lda);
#pragma unroll
            for (int i = 0; i < NBC; i++)
                CPASYNC(dB + i * (16 * LDSA * 4), gB + koff + (long)i * 16 * ldb);
            asm volatile("cp.async.commit_group;" ::: "memory");
        }

        const float* as = As[kt & 1];
        const float* bs = Bs[kt & 1];

        if (MODE == 0) {
            // ---- BF16X2: 2 k-steps of 16, 3 bf16 MMAs per (i,j)
#pragma unroll
            for (int ks = 0; ks < 2; ks++) {
                const int k0 = ks * 16 + 2 * tg;
                uint32_t ah[4][4], al[4][4], bh[NF][2], bl[NF][2];
#pragma unroll
                for (int i = 0; i < 4; i++) {
                    const float* ap = as + (wm + i * 16 + gid) * LDSA + k0;
                    float2 p0 = *(const float2*)(ap);
                    float2 p1 = *(const float2*)(ap + 8 * LDSA);
                    float2 p2 = *(const float2*)(ap + 8);
                    float2 p3 = *(const float2*)(ap + 8 * LDSA + 8);
                    split_pair(p0.x, p0.y, ah[i][0], al[i][0]);
                    split_pair(p1.x, p1.y, ah[i][1], al[i][1]);
                    split_pair(p2.x, p2.y, ah[i][2], al[i][2]);
                    split_pair(p3.x, p3.y, ah[i][3], al[i][3]);
                }
#pragma unroll
                for (int j = 0; j < NF; j++) {
                    const float* bp = bs + (wn + j * 8 + gid) * LDSA + k0;
                    float2 p0 = *(const float2*)(bp);
                    float2 p1 = *(const float2*)(bp + 8);
                    split_pair(p0.x, p0.y, bh[j][0], bl[j][0]);
                    split_pair(p1.x, p1.y, bh[j][1], bl[j][1]);
                }
#pragma unroll
                for (int i = 0; i < 4; i++)
#pragma unroll
                    for (int j = 0; j < NF; j++) {
                        mma_bf16(acc[i][j], ah[i], bh[j]);
                        mma_bf16(acc[i][j], ah[i], bl[j]);
                        mma_bf16(acc[i][j], al[i], bh[j]);
                    }
            }
        } else {
            // ---- plain tf32: 4 k-steps of 8, 1 MMA per (i,j)
#pragma unroll
            for (int ks = 0; ks < 4; ks++) {
                const int k0 = ks * 8;
                uint32_t ah[4][4], bh[NF][2];
#pragma unroll
                for (int i = 0; i < 4; i++) {
                    const float* ap = as + (wm + i * 16 + gid) * LDSA + k0 + tg;
                    ah[i][0] = f2tf32(ap[0]);
                    ah[i][2] = f2tf32(ap[4]);
                    ah[i][1] = f2tf32(ap[8 * LDSA]);
                    ah[i][3] = f2tf32(ap[8 * LDSA + 4]);
                }
#pragma unroll
                for (int j = 0; j < NF; j++) {
                    const float* bp = bs + (wn + j * 8 + gid) * LDSA + k0 + tg;
                    bh[j][0] = f2tf32(bp[0]);
                    bh[j][1] = f2tf32(bp[4]);
                }
#pragma unroll
                for (int i = 0; i < 4; i++)
#pragma unroll
                    for (int j = 0; j < NF; j++)
                        mma_tf32(acc[i][j], ah[i], bh[j]);
            }
        }
    }

    // epilogue
#pragma unroll
    for (int i = 0; i < 4; i++) {
        const int row = m0 + wm + i * 16 + gid;
        float bv0 = 0.f, bv8 = 0.f;
        if (bias_mode == 1) { bv0 = bias[row]; bv8 = bias[row + 8]; }
#pragma unroll
        for (int j = 0; j < NF; j++) {
            const int col = n0 + wn + j * 8 + tg * 2;
            float c0 = acc[i][j][0], c1 = acc[i][j][1];
            float c2 = acc[i][j][2], c3 = acc[i][j][3];
            if (bias_mode == 1) { c0 += bv0; c1 += bv0; c2 += bv8; c3 += bv8; }
            else if (bias_mode == 2) {
                float b0 = bias[col], b1 = bias[col + 1];
                c0 += b0; c1 += b1; c2 += b0; c3 += b1;
            }
            *(float2*)&Csel[(long)row * ldc + col] = make_float2(c0, c1);
            *(float2*)&Csel[(long)(row + 8) * ldc + col] = make_float2(c2, c3);
        }
    }
}

// ---------------------------------------------------------------------------
// im2col transposed: colT[b][p][ic*9+k], p in 24x24, stride2 pad1
// ---------------------------------------------------------------------------
__global__ void im2colT_kernel(const float* __restrict__ x, float* __restrict__ colT) {
    long idx = (long)blockIdx.x * 256 + threadIdx.x;
    const long total = 8L * 576 * 4608;
    if (idx >= total) return;
    int r = (int)(idx % 4608);
    long t = idx / 4608;
    int p = (int)(t % 576);
    int b = (int)(t / 576);
    int ic = r / 9, k = r % 9;
    int ky = k / 3, kx = k % 3;
    int oy = p / 24, ox = p % 24;
    int iy = oy * 2 - 1 + ky;
    int ix = ox * 2 - 1 + kx;
    float v = 0.0f;
    if ((unsigned)iy < 48u && (unsigned)ix < 48u)
        v = x[((long)(b * 512 + ic) * 48 + iy) * 48 + ix];
    colT[idx] = v;
}

// ---------------------------------------------------------------------------
// x transpose: xT[b][p][c] = x[b][c][p]
// ---------------------------------------------------------------------------
__global__ void transpose_x_kernel(const float* __restrict__ x, float* __restrict__ xT) {
    __shared__ float t[32][33];
    int b = blockIdx.z;
    int p0 = blockIdx.x * 32, c0 = blockIdx.y * 32;
    const float* xb = x + (long)b * 512 * 2304;
    float* ob = xT + (long)b * 2304 * 512;
    int tx = threadIdx.x, ty = threadIdx.y;   // (32, 8)
#pragma unroll
    for (int j = 0; j < 32; j += 8)
        t[ty + j][tx] = xb[(long)(c0 + ty + j) * 2304 + p0 + tx];
    __syncthreads();
#pragma unroll
    for (int j = 0; j < 32; j += 8)
        ob[(long)(p0 + ty + j) * 512 + c0 + tx] = t[tx][ty + j];
}

// concat Wqc(1024x4608) || Wkc(512x4608)
__global__ void concat_wc_kernel(const float* __restrict__ Wqc, const float* __restrict__ Wkc,
                                 float* __restrict__ W) {
    long i = (long)blockIdx.x * 256 + threadIdx.x;
    if (i >= 1536L * 4608) return;
    W[i] = (i < 1024L * 4608) ? Wqc[i] : Wkc[i - 1024L * 4608];
}
// concat Wqp(64x512) || Wkp(64x512)
__global__ void concat_wp_kernel(const float* __restrict__ Wqp, const float* __restrict__ Wkp,
                                 float* __restrict__ W) {
    int i = blockIdx.x * 256 + threadIdx.x;
    if (i >= 128 * 512) return;
    W[i] = (i < 64 * 512) ? Wqp[i] : Wkp[i - 64 * 512];
}
// concat biases: bqckc[1536] = bqc||bkc ; bqkp[128] = bqp||bkp
__global__ void concat_bias_kernel(const float* bqc, const float* bkc,
                                   const float* bqp, const float* bkp,
                                   float* bqckc, float* bqkp) {
    int i = blockIdx.x * 256 + threadIdx.x;
    if (i < 1024) bqckc[i] = bqc[i];
    else if (i < 1536) bqckc[i] = bkc[i - 1024];
    else if (i < 1600) bqkp[i - 1536] = bqp[i - 1536];
    else if (i < 1664) bqkp[i - 1536] = bkp[i - 1600];
}

// ---------------------------------------------------------------------------
// CAM softmax: rows of 512. softmax(max(e)-e) == exp(min(e)-e)/sum. In place.
// ---------------------------------------------------------------------------
__global__ void softmax_c_kernel(float* __restrict__ E) {
    float* row = E + (long)blockIdx.x * 512;
    int tid = threadIdx.x;  // 128
    float vals[4];
    float mn = 3.4e38f;
#pragma unroll
    for (int c = 0; c < 4; c++) {
        vals[c] = row[tid + c * 128];
        mn = fminf(mn, vals[c]);
    }
#pragma unroll
    for (int o = 16; o; o >>= 1) mn = fminf(mn, __shfl_xor_sync(~0u, mn, o));
    __shared__ float shm[4];
    if ((tid & 31) == 0) shm[tid >> 5] = mn;
    __syncthreads();
    mn = fminf(fminf(shm[0], shm[1]), fminf(shm[2], shm[3]));
    float s = 0.0f;
#pragma unroll
    for (int c = 0; c < 4; c++) {
        vals[c] = __expf(mn - vals[c]);
        s += vals[c];
    }
#pragma unroll
    for (int o = 16; o; o >>= 1) s += __shfl_xor_sync(~0u, s, o);
    __shared__ float shs[4];
    if ((tid & 31) == 0) shs[tid >> 5] = s;
    __syncthreads();
    s = shs[0] + shs[1] + shs[2] + shs[3];
    float r = 1.0f / s;
#pragma unroll
    for (int c = 0; c < 4; c++) row[tid + c * 128] = vals[c] * r;
}

// ---------------------------------------------------------------------------
// PAM softmax: rows of 2304, in place
// ---------------------------------------------------------------------------
__global__ void softmax_p_kernel(float* __restrict__ E) {
    float* row = E + (long)blockIdx.x * 2304;
    int tid = threadIdx.x;  // 256
    float vals[9];
    float mx = -3.4e38f;
#pragma unroll
    for (int c = 0; c < 9; c++) {
        vals[c] = row[tid + c * 256];
        mx = fmaxf(mx, vals[c]);
    }
#pragma unroll
    for (int o = 16; o; o >>= 1) mx = fmaxf(mx, __shfl_xor_sync(~0u, mx, o));
    __shared__ float shm[8];
    if ((tid & 31) == 0) shm[tid >> 5] = mx;
    __syncthreads();
    mx = shm[0];
#pragma unroll
    for (int i = 1; i < 8; i++) mx = fmaxf(mx, shm[i]);
    float s = 0.0f;
#pragma unroll
    for (int c = 0; c < 9; c++) {
        vals[c] = __expf(vals[c] - mx);
        s += vals[c];
    }
#pragma unroll
    for (int o = 16; o; o >>= 1) s += __shfl_xor_sync(~0u, s, o);
    __shared__ float shs[8];
    if ((tid & 31) == 0) shs[tid >> 5] = s;
    __syncthreads();
    s = 0.0f;
#pragma unroll
    for (int i = 0; i < 8; i++) s += shs[i];
    float r = 1.0f / s;
#pragma unroll
    for (int c = 0; c < 9; c++) row[tid + c * 256] = vals[c] * r;
}

// ---------------------------------------------------------------------------
// Host
// ---------------------------------------------------------------------------
template <int MODE, int NF>
static void launch_gemm(const float* A, const float* B, float* C, const float* bias,
                        const float* B2, float* C2, int nsplit,
                        int M, int N, int K, int lda, int ldb, int ldc,
                        long sA, long sB, long sC, int bias_mode) {
    constexpr int BN = NF * 16;
    constexpr int SMEM = (2 * 128 * LDSA + 2 * BN * LDSA) * 4;
    cudaFuncSetAttribute(mma_gemm<MODE, NF>, cudaFuncAttributeMaxDynamicSharedMemorySize, SMEM);
    dim3 g(N / BN, M / GBM, BATCH);
    mma_gemm<MODE, NF><<<g, 128, SMEM>>>(A, B, C, bias, B2, C2, nsplit,
                                         M, N, K, lda, ldb, ldc, sA, sB, sC, bias_mode);
}

extern "C" void kernel_launch(void* const* d_in, const int* in_sizes, int n_in,
                              void* d_out, int out_size) {
    const float* x   = (const float*)d_in[0];
    const float* Wqc = (const float*)d_in[1];
    const float* bqc = (const float*)d_in[2];
    const float* Wkc = (const float*)d_in[3];
    const float* bkc = (const float*)d_in[4];
    const float* Wqp = (const float*)d_in[5];
    const float* bqp = (const float*)d_in[6];
    const float* Wkp = (const float*)d_in[7];
    const float* bkp = (const float*)d_in[8];

    void* sp = nullptr;
    cudaGetSymbolAddress(&sp, g_scratch);
    float* S = (float*)sp;
    float* colT  = S + OFF_COLT;
    float* xT    = S + OFF_XT;
    float* wqckc = S + OFF_WQCKC;
    float* wqkp  = S + OFF_WQKP;
    float* qckc  = S + OFF_QCKC;
    float* energy = S + OFF_EN;    // -> attn_c in place
    float* qkpt  = S + OFF_QKPT;
    float* ep    = S + OFF_EP;     // -> attn_p in place
    float* tT    = S + OFF_TT;     // tT[b][m][c] = sum_n attn_p[m][n]*x[b][c][n]
    float* bias_ckc = S + OFF_BIAS;
    float* bias_qkp = S + OFF_BIAS + 2048;

    float* out_c = (float*)d_out;                 // (8,1024,2304)
    float* out_p = out_c + 8L * 1024 * 2304;      // (8,1024,48,48)

    const int NOSPLIT = 1 << 30;

    // layout passes
    {
        long total = 8L * 576 * 4608;
        im2colT_kernel<<<(unsigned)((total + 255) / 256), 256>>>(x, colT);
    }
    transpose_x_kernel<<<dim3(72, 16, 8), dim3(32, 8)>>>(x, xT);
    concat_wc_kernel<<<(unsigned)((1536L * 4608 + 255) / 256), 256>>>(Wqc, Wkc, wqckc);
    concat_wp_kernel<<<(128 * 512 + 255) / 256, 256>>>(Wqp, Wkp, wqkp);
    concat_bias_kernel<<<7, 256>>>(bqc, bkc, bqp, bkp, bias_ckc, bias_qkp);

    // G1: [qc;kc] = Wqckc * colT^T + b       (M=1536, N=576, K=4608)  bf16x2, NF=6
    launch_gemm<0, 6>(wqckc, colT, qckc, bias_ckc, colT, qckc, NOSPLIT,
                      1536, 576, 4608, 4608, 4608, 576, 0, 576L * 4608, 1536L * 576, 1);
    // G2: energy = qc * kc^T                 (M=1024, N=512, K=576)   bf16x2, NF=8
    launch_gemm<0, 8>(qckc, qckc + 1024L * 576, energy, nullptr,
                      qckc + 1024L * 576, energy, NOSPLIT,
                      1024, 512, 576, 576, 576, 512, 1536L * 576, 1536L * 576, 1024L * 512, 0);
    // softmax_c in place (energy -> attn_c, fp32)
    softmax_c_kernel<<<8 * 1024, 128>>>(energy);
    // G4: [qp;kp]^T = xT * Wqkp^T + b        (M=2304, N=128, K=512)   bf16x2, NF=4
    launch_gemm<0, 4>(xT, wqkp, qkpt, bias_qkp, wqkp, qkpt, NOSPLIT,
                      2304, 128, 512, 512, 512, 128, 2304L * 512, 0, 2304L * 128, 2);
    // G5: energy_p = qpT * kpT^T             (M=2304, N=2304, K=64)   bf16x2, NF=8
    launch_gemm<0, 8>(qkpt, qkpt + 64, ep, nullptr, qkpt + 64, ep, NOSPLIT,
                      2304, 2304, 64, 128, 128, 2304, 2304L * 128, 2304L * 128, 2304L * 2304, 0);
    // softmax_p in place (ep -> attn_p, fp32)
    softmax_p_kernel<<<8 * 2304, 256>>>(ep);
    // G6a: tT = attn_p *NT x                 (M=2304, N=512, K=2304)  tf32, NF=8
    launch_gemm<1, 8>(ep, x, tT, nullptr, x, tT, NOSPLIT,
                      2304, 512, 2304, 2304, 2304, 512,
                      2304L * 2304, 512L * 2304, 2304L * 512, 0);
    // G36 fused: [out_c | out_p] = attn_c *NT [xT | tT]
    //            (M=1024, N=4608 split at 2304, K=512)  tf32, NF=8
    launch_gemm<1, 8>(energy, xT, out_c, nullptr, tT, out_p, 2304,
                      1024, 4608, 512, 512, 512, 2304,
                      1024L * 512, 2304L * 512, 1024L * 2304, 0);
}

// round 17
// speedup vs baseline: 1.5161x; 1.5161x over previous
#include <cuda_runtime.h>
#include <math.h>
#include <stdint.h>

// ---------------------------------------------------------------------------
// Problem: B=8, C=512, H=W=48 (HW=2304); stride-2 conv -> 24x24=576
// All GEMMs in NT form: C[M,N] = A[M,K] * B[N,K]^T.
// MODE 0: BF16X2 compensated (3 bf16 m16n8k16 MMAs per k16) -- pre-softmax
//         chain (G1, G2, G4, G5).
// MODE 1: plain tf32 m16n8k8 -- post-softmax stages (G3, G6a, G6b).
// fp16.f32-accum measured SLOW on sm_103 -- do not use.
// G6 re-associated: out_p = attn_c * (attn_p * xf^T)^T  (28% fewer MACs).
// G1 runs NF=6 (BN=96; 576%96==0). 2-stage cp.async (3-stage, reg caps,
// pre-split operands, and split-N fusion all measured worse -- keep template
// untouched; only isolated single-site changes have matched predictions).
// ---------------------------------------------------------------------------
#define BATCH 8

// scratch layout (floats)
#define SZ_COLT  (8L*576*4608)
#define SZ_XT    (8L*2304*512)
#define SZ_WQCKC (1536L*4608)
#define SZ_WQKP  (128L*512)
#define SZ_QCKC  (8L*1536*576)
#define SZ_EN    (8L*1024*512)
#define SZ_QKPT  (8L*2304*128)
#define SZ_EP    (8L*2304*2304)
#define SZ_TT    (8L*2304*512)

#define OFF_COLT  0L
#define OFF_XT    (OFF_COLT + SZ_COLT)
#define OFF_WQCKC (OFF_XT + SZ_XT)
#define OFF_WQKP  (OFF_WQCKC + SZ_WQCKC)
#define OFF_QCKC  (OFF_WQKP + SZ_WQKP)
#define OFF_EN    (OFF_QCKC + SZ_QCKC)
#define OFF_QKPT  (OFF_EN + SZ_EN)
#define OFF_EP    (OFF_QKPT + SZ_QKPT)
#define OFF_TT    (OFF_EP + SZ_EP)
#define OFF_BIAS  (OFF_TT + SZ_TT)
#define SZ_TOTAL  (OFF_BIAS + 4096)

__device__ float g_scratch[SZ_TOTAL];

// ---------------------------------------------------------------------------
// helpers
// ---------------------------------------------------------------------------
__device__ __forceinline__ uint32_t f2tf32(float f) {
    uint32_t u;
    asm("cvt.rna.tf32.f32 %0, %1;" : "=r"(u) : "f"(f));
    return u;
}
__device__ __forceinline__ void mma_tf32(float* d, const uint32_t* a, const uint32_t* b) {
    asm volatile(
        "mma.sync.aligned.m16n8k8.row.col.f32.tf32.tf32.f32 "
        "{%0,%1,%2,%3}, {%4,%5,%6,%7}, {%8,%9}, {%0,%1,%2,%3};"
        : "+f"(d[0]), "+f"(d[1]), "+f"(d[2]), "+f"(d[3])
        : "r"(a[0]), "r"(a[1]), "r"(a[2]), "r"(a[3]), "r"(b[0]), "r"(b[1]));
}
__device__ __forceinline__ void mma_bf16(float* d, const uint32_t* a, const uint32_t* b) {
    asm volatile(
        "mma.sync.aligned.m16n8k16.row.col.f32.bf16.bf16.f32 "
        "{%0,%1,%2,%3}, {%4,%5,%6,%7}, {%8,%9}, {%0,%1,%2,%3};"
        : "+f"(d[0]), "+f"(d[1]), "+f"(d[2]), "+f"(d[3])
        : "r"(a[0]), "r"(a[1]), "r"(a[2]), "r"(a[3]), "r"(b[0]), "r"(b[1]));
}
// hi = truncate-to-bf16 (exact in fp32), lo = bf16(f - hi). Pack k,k+1 pairs.
__device__ __forceinline__ void split_pair(float f0, float f1, uint32_t& h, uint32_t& l) {
    uint32_t u0 = __float_as_uint(f0), u1 = __float_as_uint(f1);
    h = __byte_perm(u0, u1, 0x7632);               // {f1.hi16, f0.hi16}
    float l0 = f0 - __uint_as_float(u0 & 0xFFFF0000u);
    float l1 = f1 - __uint_as_float(u1 & 0xFFFF0000u);
    asm("cvt.rn.bf16x2.f32 %0, %1, %2;" : "=r"(l) : "f"(l1), "f"(l0));
}
#define CPASYNC(dst, src) \
    asm volatile("cp.async.cg.shared.global [%0], [%1], 16;" :: "r"(dst), "l"(src) : "memory")

// ---------------------------------------------------------------------------
// NT GEMM via warp MMA. 128 threads (4 warps, 2x2). Block 128 x (NF*16) x 32.
// Warp tile 64 x (NF*8). SMEM rows padded to 36 floats. 2-stage cp.async.
// Requires M%128==0, N%(NF*16)==0, K%32==0.
// ---------------------------------------------------------------------------
#define GBM 128
#define GBK 32
#define LDSA 36

template <int MODE, int NF>
__global__ __launch_bounds__(128) void mma_gemm(
    const float* __restrict__ A, const float* __restrict__ B,
    float* __restrict__ C, const float* __restrict__ bias,
    int M, int N, int K, int lda, int ldb, int ldc,
    long sA, long sB, long sC, int bias_mode)
{
    constexpr int BN = NF * 16;
    constexpr int A_FL = 128 * LDSA;
    constexpr int B_FL = BN * LDSA;
    constexpr int NBC = BN / 16;

    extern __shared__ float sm[];
    float* As[2] = { sm, sm + A_FL };
    float* Bs[2] = { sm + 2 * A_FL, sm + 2 * A_FL + B_FL };

    const int tid = threadIdx.x;
    const int bz = blockIdx.z;
    A += (long)bz * sA;
    B += (long)bz * sB;
    C += (long)bz * sC;
    const int m0 = blockIdx.y * GBM;
    const int n0 = blockIdx.x * BN;

    // cp.async mapping: 16B chunks, rows strided by 16
    const int c8 = tid & 7;
    const int r0 = tid >> 3;
    const float* gA = A + (long)(m0 + r0) * lda + c8 * 4;
    const float* gB = B + (long)(n0 + r0) * ldb + c8 * 4;
    uint32_t sA0 = (uint32_t)__cvta_generic_to_shared(As[0] + r0 * LDSA + c8 * 4);
    uint32_t sA1 = (uint32_t)__cvta_generic_to_shared(As[1] + r0 * LDSA + c8 * 4);
    uint32_t sB0 = (uint32_t)__cvta_generic_to_shared(Bs[0] + r0 * LDSA + c8 * 4);
    uint32_t sB1 = (uint32_t)__cvta_generic_to_shared(Bs[1] + r0 * LDSA + c8 * 4);

    const int NT = K / GBK;

    const int warp = tid >> 5, lane = tid & 31;
    const int wm = (warp & 1) * 64;
    const int wn = (warp >> 1) * (NF * 8);
    const int gid = lane >> 2, tg = lane & 3;

    float acc[4][NF][4];
#pragma unroll
    for (int i = 0; i < 4; i++)
#pragma unroll
        for (int j = 0; j < NF; j++)
#pragma unroll
            for (int c = 0; c < 4; c++) acc[i][j][c] = 0.0f;

    // prologue: stage 0
    {
#pragma unroll
        for (int i = 0; i < 8; i++)
            CPASYNC(sA0 + i * (16 * LDSA * 4), gA + (long)i * 16 * lda);
#pragma unroll
        for (int i = 0; i < NBC; i++)
            CPASYNC(sB0 + i * (16 * LDSA * 4), gB + (long)i * 16 * ldb);
        asm volatile("cp.async.commit_group;" ::: "memory");
    }

    for (int kt = 0; kt < NT; kt++) {
        asm volatile("cp.async.wait_group 0;" ::: "memory");
        __syncthreads();

        if (kt + 1 < NT) {
            const long koff = (long)(kt + 1) * GBK;
            const uint32_t dA = ((kt + 1) & 1) ? sA1 : sA0;
            const uint32_t dB = ((kt + 1) & 1) ? sB1 : sB0;
#pragma unroll
            for (int i = 0; i < 8; i++)
                CPASYNC(dA + i * (16 * LDSA * 4), gA + koff + (long)i * 16 * lda);
#pragma unroll
            for (int i = 0; i < NBC; i++)
                CPASYNC(dB + i * (16 * LDSA * 4), gB + koff + (long)i * 16 * ldb);
            asm volatile("cp.async.commit_group;" ::: "memory");
        }

        const float* as = As[kt & 1];
        const float* bs = Bs[kt & 1];

        if (MODE == 0) {
            // ---- BF16X2: 2 k-steps of 16, 3 bf16 MMAs per (i,j)
#pragma unroll
            for (int ks = 0; ks < 2; ks++) {
                const int k0 = ks * 16 + 2 * tg;
                uint32_t ah[4][4], al[4][4], bh[NF][2], bl[NF][2];
#pragma unroll
                for (int i = 0; i < 4; i++) {
                    const float* ap = as + (wm + i * 16 + gid) * LDSA + k0;
                    float2 p0 = *(const float2*)(ap);
                    float2 p1 = *(const float2*)(ap + 8 * LDSA);
                    float2 p2 = *(const float2*)(ap + 8);
                    float2 p3 = *(const float2*)(ap + 8 * LDSA + 8);
                    split_pair(p0.x, p0.y, ah[i][0], al[i][0]);
                    split_pair(p1.x, p1.y, ah[i][1], al[i][1]);
                    split_pair(p2.x, p2.y, ah[i][2], al[i][2]);
                    split_pair(p3.x, p3.y, ah[i][3], al[i][3]);
                }
#pragma unroll
                for (int j = 0; j < NF; j++) {
                    const float* bp = bs + (wn + j * 8 + gid) * LDSA + k0;
                    float2 p0 = *(const float2*)(bp);
                    float2 p1 = *(const float2*)(bp + 8);
                    split_pair(p0.x, p0.y, bh[j][0], bl[j][0]);
                    split_pair(p1.x, p1.y, bh[j][1], bl[j][1]);
                }
#pragma unroll
                for (int i = 0; i < 4; i++)
#pragma unroll
                    for (int j = 0; j < NF; j++) {
                        mma_bf16(acc[i][j], ah[i], bh[j]);
                        mma_bf16(acc[i][j], ah[i], bl[j]);
                        mma_bf16(acc[i][j], al[i], bh[j]);
                    }
            }
        } else {
            // ---- plain tf32: 4 k-steps of 8, 1 MMA per (i,j)
#pragma unroll
            for (int ks = 0; ks < 4; ks++) {
                const int k0 = ks * 8;
                uint32_t ah[4][4], bh[NF][2];
#pragma unroll
                for (int i = 0; i < 4; i++) {
                    const float* ap = as + (wm + i * 16 + gid) * LDSA + k0 + tg;
                    ah[i][0] = f2tf32(ap[0]);
                    ah[i][2] = f2tf32(ap[4]);
                    ah[i][1] = f2tf32(ap[8 * LDSA]);
                    ah[i][3] = f2tf32(ap[8 * LDSA + 4]);
                }
#pragma unroll
                for (int j = 0; j < NF; j++) {
                    const float* bp = bs + (wn + j * 8 + gid) * LDSA + k0 + tg;
                    bh[j][0] = f2tf32(bp[0]);
                    bh[j][1] = f2tf32(bp[4]);
                }
#pragma unroll
                for (int i = 0; i < 4; i++)
#pragma unroll
                    for (int j = 0; j < NF; j++)
                        mma_tf32(acc[i][j], ah[i], bh[j]);
            }
        }
    }

    // epilogue
#pragma unroll
    for (int i = 0; i < 4; i++) {
        const int row = m0 + wm + i * 16 + gid;
        float bv0 = 0.f, bv8 = 0.f;
        if (bias_mode == 1) { bv0 = bias[row]; bv8 = bias[row + 8]; }
#pragma unroll
        for (int j = 0; j < NF; j++) {
            const int col = n0 + wn + j * 8 + tg * 2;
            float c0 = acc[i][j][0], c1 = acc[i][j][1];
            float c2 = acc[i][j][2], c3 = acc[i][j][3];
            if (bias_mode == 1) { c0 += bv0; c1 += bv0; c2 += bv8; c3 += bv8; }
            else if (bias_mode == 2) {
                float b0 = bias[col], b1 = bias[col + 1];
                c0 += b0; c1 += b1; c2 += b0; c3 += b1;
            }
            *(float2*)&C[(long)row * ldc + col] = make_float2(c0, c1);
            *(float2*)&C[(long)(row + 8) * ldc + col] = make_float2(c2, c3);
        }
    }
}

// ---------------------------------------------------------------------------
// im2col transposed: colT[b][p][ic*9+k], p in 24x24, stride2 pad1
// ---------------------------------------------------------------------------
__global__ void im2colT_kernel(const float* __restrict__ x, float* __restrict__ colT) {
    long idx = (long)blockIdx.x * 256 + threadIdx.x;
    const long total = 8L * 576 * 4608;
    if (idx >= total) return;
    int r = (int)(idx % 4608);
    long t = idx / 4608;
    int p = (int)(t % 576);
    int b = (int)(t / 576);
    int ic = r / 9, k = r % 9;
    int ky = k / 3, kx = k % 3;
    int oy = p / 24, ox = p % 24;
    int iy = oy * 2 - 1 + ky;
    int ix = ox * 2 - 1 + kx;
    float v = 0.0f;
    if ((unsigned)iy < 48u && (unsigned)ix < 48u)
        v = x[((long)(b * 512 + ic) * 48 + iy) * 48 + ix];
    colT[idx] = v;
}

// ---------------------------------------------------------------------------
// x transpose: xT[b][p][c] = x[b][c][p]
// ---------------------------------------------------------------------------
__global__ void transpose_x_kernel(const float* __restrict__ x, float* __restrict__ xT) {
    __shared__ float t[32][33];
    int b = blockIdx.z;
    int p0 = blockIdx.x * 32, c0 = blockIdx.y * 32;
    const float* xb = x + (long)b * 512 * 2304;
    float* ob = xT + (long)b * 2304 * 512;
    int tx = threadIdx.x, ty = threadIdx.y;   // (32, 8)
#pragma unroll
    for (int j = 0; j < 32; j += 8)
        t[ty + j][tx] = xb[(long)(c0 + ty + j) * 2304 + p0 + tx];
    __syncthreads();
#pragma unroll
    for (int j = 0; j < 32; j += 8)
        ob[(long)(p0 + ty + j) * 512 + c0 + tx] = t[tx][ty + j];
}

// concat Wqc(1024x4608) || Wkc(512x4608)
__global__ void concat_wc_kernel(const float* __restrict__ Wqc, const float* __restrict__ Wkc,
                                 float* __restrict__ W) {
    long i = (long)blockIdx.x * 256 + threadIdx.x;
    if (i >= 1536L * 4608) return;
    W[i] = (i < 1024L * 4608) ? Wqc[i] : Wkc[i - 1024L * 4608];
}
// concat Wqp(64x512) || Wkp(64x512)
__global__ void concat_wp_kernel(const float* __restrict__ Wqp, const float* __restrict__ Wkp,
                                 float* __restrict__ W) {
    int i = blockIdx.x * 256 + threadIdx.x;
    if (i >= 128 * 512) return;
    W[i] = (i < 64 * 512) ? Wqp[i] : Wkp[i - 64 * 512];
}
// concat biases: bqckc[1536] = bqc||bkc ; bqkp[128] = bqp||bkp
__global__ void concat_bias_kernel(const float* bqc, const float* bkc,
                                   const float* bqp, const float* bkp,
                                   float* bqckc, float* bqkp) {
    int i = blockIdx.x * 256 + threadIdx.x;
    if (i < 1024) bqckc[i] = bqc[i];
    else if (i < 1536) bqckc[i] = bkc[i - 1024];
    else if (i < 1600) bqkp[i - 1536] = bqp[i - 1536];
    else if (i < 1664) bqkp[i - 1536] = bkp[i - 1600];
}

// ---------------------------------------------------------------------------
// CAM softmax: rows of 512. softmax(max(e)-e) == exp(min(e)-e)/sum. In place.
// ---------------------------------------------------------------------------
__global__ void softmax_c_kernel(float* __restrict__ E) {
    float* row = E + (long)blockIdx.x * 512;
    int tid = threadIdx.x;  // 128
    float vals[4];
    float mn = 3.4e38f;
#pragma unroll
    for (int c = 0; c < 4; c++) {
        vals[c] = row[tid + c * 128];
        mn = fminf(mn, vals[c]);
    }
#pragma unroll
    for (int o = 16; o; o >>= 1) mn = fminf(mn, __shfl_xor_sync(~0u, mn, o));
    __shared__ float shm[4];
    if ((tid & 31) == 0) shm[tid >> 5] = mn;
    __syncthreads();
    mn = fminf(fminf(shm[0], shm[1]), fminf(shm[2], shm[3]));
    float s = 0.0f;
#pragma unroll
    for (int c = 0; c < 4; c++) {
        vals[c] = __expf(mn - vals[c]);
        s += vals[c];
    }
#pragma unroll
    for (int o = 16; o; o >>= 1) s += __shfl_xor_sync(~0u, s, o);
    __shared__ float shs[4];
    if ((tid & 31) == 0) shs[tid >> 5] = s;
    __syncthreads();
    s = shs[0] + shs[1] + shs[2] + shs[3];
    float r = 1.0f / s;
#pragma unroll
    for (int c = 0; c < 4; c++) row[tid + c * 128] = vals[c] * r;
}

// ---------------------------------------------------------------------------
// PAM softmax: rows of 2304, in place
// ---------------------------------------------------------------------------
__global__ void softmax_p_kernel(float* __restrict__ E) {
    float* row = E + (long)blockIdx.x * 2304;
    int tid = threadIdx.x;  // 256
    float vals[9];
    float mx = -3.4e38f;
#pragma unroll
    for (int c = 0; c < 9; c++) {
        vals[c] = row[tid + c * 256];
        mx = fmaxf(mx, vals[c]);
    }
#pragma unroll
    for (int o = 16; o; o >>= 1) mx = fmaxf(mx, __shfl_xor_sync(~0u, mx, o));
    __shared__ float shm[8];
    if ((tid & 31) == 0) shm[tid >> 5] = mx;
    __syncthreads();
    mx = shm[0];
#pragma unroll
    for (int i = 1; i < 8; i++) mx = fmaxf(mx, shm[i]);
    float s = 0.0f;
#pragma unroll
    for (int c = 0; c < 9; c++) {
        vals[c] = __expf(vals[c] - mx);
        s += vals[c];
    }
#pragma unroll
    for (int o = 16; o; o >>= 1) s += __shfl_xor_sync(~0u, s, o);
    __shared__ float shs[8];
    if ((tid & 31) == 0) shs[tid >> 5] = s;
    __syncthreads();
    s = 0.0f;
#pragma unroll
    for (int i = 0; i < 8; i++) s += shs[i];
    float r = 1.0f / s;
#pragma unroll
    for (int c = 0; c < 9; c++) row[tid + c * 256] = vals[c] * r;
}

// ---------------------------------------------------------------------------
// Host
// ---------------------------------------------------------------------------
template <int MODE, int NF>
static void launch_gemm(const float* A, const float* B, float* C, const float* bias,
                        int M, int N, int K, int lda, int ldb, int ldc,
                        long sA, long sB, long sC, int bias_mode) {
    constexpr int BN = NF * 16;
    constexpr int SMEM = (2 * 128 * LDSA + 2 * BN * LDSA) * 4;
    cudaFuncSetAttribute(mma_gemm<MODE, NF>, cudaFuncAttributeMaxDynamicSharedMemorySize, SMEM);
    dim3 g(N / BN, M / GBM, BATCH);
    mma_gemm<MODE, NF><<<g, 128, SMEM>>>(A, B, C, bias, M, N, K, lda, ldb, ldc,
                                         sA, sB, sC, bias_mode);
}

extern "C" void kernel_launch(void* const* d_in, const int* in_sizes, int n_in,
                              void* d_out, int out_size) {
    const float* x   = (const float*)d_in[0];
    const float* Wqc = (const float*)d_in[1];
    const float* bqc = (const float*)d_in[2];
    const float* Wkc = (const float*)d_in[3];
    const float* bkc = (const float*)d_in[4];
    const float* Wqp = (const float*)d_in[5];
    const float* bqp = (const float*)d_in[6];
    const float* Wkp = (const float*)d_in[7];
    const float* bkp = (const float*)d_in[8];

    void* sp = nullptr;
    cudaGetSymbolAddress(&sp, g_scratch);
    float* S = (float*)sp;
    float* colT  = S + OFF_COLT;
    float* xT    = S + OFF_XT;
    float* wqckc = S + OFF_WQCKC;
    float* wqkp  = S + OFF_WQKP;
    float* qckc  = S + OFF_QCKC;
    float* energy = S + OFF_EN;    // -> attn_c in place
    float* qkpt  = S + OFF_QKPT;
    float* ep    = S + OFF_EP;     // -> attn_p in place
    float* tT    = S + OFF_TT;     // tT[b][m][c] = sum_n attn_p[m][n]*x[b][c][n]
    float* bias_ckc = S + OFF_BIAS;
    float* bias_qkp = S + OFF_BIAS + 2048;

    float* out_c = (float*)d_out;                 // (8,1024,2304)
    float* out_p = out_c + 8L * 1024 * 2304;      // (8,1024,48,48)

    // layout passes
    {
        long total = 8L * 576 * 4608;
        im2colT_kernel<<<(unsigned)((total + 255) / 256), 256>>>(x, colT);
    }
    transpose_x_kernel<<<dim3(72, 16, 8), dim3(32, 8)>>>(x, xT);
    concat_wc_kernel<<<(unsigned)((1536L * 4608 + 255) / 256), 256>>>(Wqc, Wkc, wqckc);
    concat_wp_kernel<<<(128 * 512 + 255) / 256, 256>>>(Wqp, Wkp, wqkp);
    concat_bias_kernel<<<7, 256>>>(bqc, bkc, bqp, bkp, bias_ckc, bias_qkp);

    // G1: [qc;kc] = Wqckc * colT^T + b       (M=1536, N=576, K=4608)  bf16x2, NF=6
    launch_gemm<0, 6>(wqckc, colT, qckc, bias_ckc,
                      1536, 576, 4608, 4608, 4608, 576, 0, 576L * 4608, 1536L * 576, 1);
    // G2: energy = qc * kc^T                 (M=1024, N=512, K=576)   bf16x2, NF=8
    launch_gemm<0, 8>(qckc, qckc + 1024L * 576, energy, nullptr,
                      1024, 512, 576, 576, 576, 512, 1536L * 576, 1536L * 576, 1024L * 512, 0);
    // softmax_c in place (energy -> attn_c, fp32)
    softmax_c_kernel<<<8 * 1024, 128>>>(energy);
    // G3: out_c = attn_c * xT^T              (M=1024, N=2304, K=512)  tf32, NF=8
    //     (post-softmax leaf output: single-pass tf32 is sufficient)
    launch_gemm<1, 8>(energy, xT, out_c, nullptr,
                      1024, 2304, 512, 512, 512, 2304, 1024L * 512, 2304L * 512, 1024L * 2304, 0);
    // G4: [qp;kp]^T = xT * Wqkp^T + b        (M=2304, N=128, K=512)   bf16x2, NF=8
    launch_gemm<0, 8>(xT, wqkp, qkpt, bias_qkp,
                      2304, 128, 512, 512, 512, 128, 2304L * 512, 0, 2304L * 128, 2);
    // G5: energy_p = qpT * kpT^T             (M=2304, N=2304, K=64)   bf16x2, NF=8
    launch_gemm<0, 8>(qkpt, qkpt + 64, ep, nullptr,
                      2304, 2304, 64, 128, 128, 2304, 2304L * 128, 2304L * 128, 2304L * 2304, 0);
    // softmax_p in place (ep -> attn_p, fp32)
    softmax_p_kernel<<<8 * 2304, 256>>>(ep);
    // G6a: tT = attn_p *NT x                 (M=2304, N=512, K=2304)  tf32, NF=8
    launch_gemm<1, 8>(ep, x, tT, nullptr,
                      2304, 512, 2304, 2304, 2304, 512,
                      2304L * 2304, 512L * 2304, 2304L * 512, 0);
    // G6b: out_p = attn_c *NT tT             (M=1024, N=2304, K=512)  tf32, NF=8
    launch_gemm<1, 8>(energy, tT, out_p, nullptr,
                      1024, 2304, 512, 512, 512, 2304,
                      1024L * 512, 2304L * 512, 1024L * 2304, 0);
}